// round 2
// baseline (speedup 1.0000x reference)
#include <cuda_runtime.h>
#include <cstdint>
#include <cstddef>

// Router: top-1 MoE routing with capacity constraint.
// Outputs (concatenated float32): dispatch[N,8,Ccap], combine[N,8,Ccap], z, aux, div, std
//
// 3 launches (graph-capturable, allocation-free):
//   1) fill_kernel:  805MB zero fill via uint4 stores (the DRAM-write roofline)
//                    + block 0 zeroes the 55 accumulators
//   2) token_kernel: softmax/argmax + warp-reduced partial sums -> g_acc
//   3) rank_scatter_kernel: stable rank per token (shared-mem broadcast brute force)
//                    + sparse scatter of <=2*8192 nonzeros + scalar finalize

#define E 8
#define MAXN 8192
#define NACC 55   // 0:z  1..8:psum  9..16:cnt  17..52:G(upper tri 36)  53:sum  54:sumsq

__device__ float g_prob[MAXN];
__device__ int   g_expert[MAXN];
__device__ float g_acc[NACC];

// ---------------------------------------------------------------- fill ----
__global__ void fill_kernel(uint4* __restrict__ out, size_t n4) {
    if (blockIdx.x == 0 && threadIdx.x < NACC) g_acc[threadIdx.x] = 0.0f;

    const uint4 z = make_uint4(0u, 0u, 0u, 0u);
    size_t i = (size_t)blockIdx.x * blockDim.x + threadIdx.x;
    size_t stride = (size_t)gridDim.x * blockDim.x;
    for (; i < n4; i += stride) out[i] = z;
}

// --------------------------------------------------------------- token ----
__global__ void token_kernel(const float* __restrict__ logits, int N) {
    int i = blockIdx.x * blockDim.x + threadIdx.x;
    float vals[NACC];
#pragma unroll
    for (int k = 0; k < NACC; k++) vals[k] = 0.0f;

    if (i < N) {
        float4 r0 = reinterpret_cast<const float4*>(logits)[2 * i + 0];
        float4 r1 = reinterpret_cast<const float4*>(logits)[2 * i + 1];
        float raw[E] = {r0.x, r0.y, r0.z, r0.w, r1.x, r1.y, r1.z, r1.w};

        float l[E];
        float s = 0.f, s2 = 0.f;
#pragma unroll
        for (int j = 0; j < E; j++) {
            s  += raw[j];
            s2 += raw[j] * raw[j];
            float c = fminf(fmaxf(raw[j], -10.0f), 10.0f);
            l[j] = c / 1.5f;                 // IEEE div, matches JAX clip/temp
        }
        vals[53] = s;
        vals[54] = s2;

        // argmax (first max) + max
        float m = l[0]; int e = 0;
#pragma unroll
        for (int j = 1; j < E; j++) {
            if (l[j] > m) { m = l[j]; e = j; }
        }

        // softmax, per-expert prob sums
        float sumexp = 0.f;
        float ex[E];
#pragma unroll
        for (int j = 0; j < E; j++) { ex[j] = expf(l[j] - m); sumexp += ex[j]; }
#pragma unroll
        for (int j = 0; j < E; j++) vals[1 + j] = ex[j] / sumexp;

        // expert_prob exactly as JAX computes it: exp(0)/sumexp
        float p = 1.0f / sumexp;
        g_prob[i]   = p;
        g_expert[i] = e;

        vals[9 + e] = 1.0f;

        float lse = m + logf(sumexp);
        vals[0] = lse * lse;

        int t = 0;
#pragma unroll
        for (int a = 0; a < E; a++)
#pragma unroll
            for (int b = a; b < E; b++) vals[17 + t++] = l[a] * l[b];
    }

    int lane = threadIdx.x & 31;
#pragma unroll
    for (int k = 0; k < NACC; k++) {
        float v = vals[k];
        v += __shfl_down_sync(0xffffffffu, v, 16);
        v += __shfl_down_sync(0xffffffffu, v, 8);
        v += __shfl_down_sync(0xffffffffu, v, 4);
        v += __shfl_down_sync(0xffffffffu, v, 2);
        v += __shfl_down_sync(0xffffffffu, v, 1);
        if (lane == 0) atomicAdd(&g_acc[k], v);
    }
}

// -------------------------------------------------------- rank + scatter ----
// Stable rank = #{j : e_j==e_i && (p_j>p_i || (p_j==p_i && j<i))}
// == JAX stable argsort(-p) followed by per-expert cumsum position.
__global__ void rank_scatter_kernel(float* __restrict__ dispatch_out,
                                    float* __restrict__ combine_out,
                                    float* __restrict__ scalars_out,
                                    int N, int Ccap) {
    __shared__ float   sp[MAXN];
    __shared__ uint8_t se[MAXN];

    for (int k = threadIdx.x; k < N; k += blockDim.x) {
        sp[k] = g_prob[k];
        se[k] = (uint8_t)g_expert[k];
    }
    __syncthreads();

    // one thread finalizes the 4 scalars (g_acc complete after token_kernel)
    if (blockIdx.x == 0 && threadIdx.x == 0) {
        float z_loss = g_acc[0] / (float)N;

        float aux = 0.f;
        for (int e = 0; e < E; e++) aux += g_acc[9 + e] * g_acc[1 + e];
        aux = aux * (float)E / ((float)N * (float)N);

        float G[E][E];
        int t = 0;
        for (int a = 0; a < E; a++)
            for (int b = a; b < E; b++) { G[a][b] = g_acc[17 + t]; G[b][a] = g_acc[17 + t]; t++; }
        float nrm[E];
        for (int a = 0; a < E; a++) nrm[a] = fmaxf(sqrtf(G[a][a]), 1e-12f);
        float div = 0.f;
        for (int a = 0; a < E; a++)
            for (int b = a + 1; b < E; b++) {
                float c = G[a][b] / (nrm[a] * nrm[b]);
                div += 2.0f * c * c;
            }
        div /= (float)(E * (E - 1));

        double M = (double)N * E;
        double sm = (double)g_acc[53], sq = (double)g_acc[54];
        double var = (sq - sm * sm / M) / (M - 1.0);

        scalars_out[0] = z_loss;
        scalars_out[1] = aux;
        scalars_out[2] = div;
        scalars_out[3] = (float)sqrt(var);
    }

    int i = blockIdx.x * blockDim.x + threadIdx.x;
    if (i >= N) return;

    float pi = sp[i];
    int   ei = se[i];
    int rank = 0;

    const float4* sp4 = reinterpret_cast<const float4*>(sp);
    const uchar4* se4 = reinterpret_cast<const uchar4*>(se);
    int n4 = N >> 2;
#pragma unroll 4
    for (int j4 = 0; j4 < n4; ++j4) {
        float4 p4 = sp4[j4];       // warp-uniform j4 -> conflict-free broadcast
        uchar4 e4 = se4[j4];
        int j = j4 << 2;
        rank += (e4.x == ei) && ((p4.x > pi) || (p4.x == pi && (j + 0) < i));
        rank += (e4.y == ei) && ((p4.y > pi) || (p4.y == pi && (j + 1) < i));
        rank += (e4.z == ei) && ((p4.z > pi) || (p4.z == pi && (j + 2) < i));
        rank += (e4.w == ei) && ((p4.w > pi) || (p4.w == pi && (j + 3) < i));
    }

    if (rank < Ccap) {
        size_t base = ((size_t)i * E + ei) * (size_t)Ccap + (size_t)rank;
        dispatch_out[base] = 1.0f;
        combine_out[base]  = pi;
    }
}

// -------------------------------------------------------------- launch ----
extern "C" void kernel_launch(void* const* d_in, const int* in_sizes, int n_in,
                              void* d_out, int out_size) {
    const float* logits = (const float*)d_in[1];
    int N = in_sizes[1] / E;                              // 8192
    int Ccap = (int)((3 * N + 2 * E - 1) / (2 * E));      // ceil(1.5*N/E) = 1536
    if (Ccap < 1) Ccap = 1;

    float* out = (float*)d_out;
    size_t D = (size_t)N * E * (size_t)Ccap;
    float* dispatch_out = out;
    float* combine_out  = out + D;
    float* scalars_out  = out + 2 * D;

    // 1) zero-fill: out_size floats = out_size/4 uint4 (exactly divisible here;
    //    guard the remainder with a tiny memset for safety)
    size_t n4 = (size_t)out_size >> 2;
    int fthreads = 256;
    int fblocks = 148 * 16;   // full chip, grid-stride, ~82 iters/thread
    fill_kernel<<<fblocks, fthreads>>>((uint4*)d_out, n4);
    size_t rem = (size_t)out_size & 3;
    if (rem) cudaMemsetAsync((float*)d_out + (out_size - rem), 0, rem * sizeof(float));

    // 2) per-token softmax/argmax + reductions
    token_kernel<<<(N + 255) / 256, 256>>>(logits, N);

    // 3) stable rank + sparse scatter + scalar finalize
    rank_scatter_kernel<<<(N + 255) / 256, 256>>>(dispatch_out, combine_out,
                                                  scalars_out, N, Ccap);
}

// round 3
// speedup vs baseline: 3.3544x; 3.3544x over previous
#include <cuda_runtime.h>
#include <cstdint>
#include <cstddef>

// Router: top-1 MoE routing with capacity constraint.
// Outputs (float32): dispatch[N,8,Ccap], combine[N,8,Ccap], z, aux, div, std
//
// 3 launches:
//   1) token_kernel: softmax/argmax, composite sort key, per-block loss partials
//   2) fill_kernel : 805MB zero fill (DRAM-bound roofline); block 0 folds partials
//   3) rank_scatter: warp-parallel branchless stable rank + sparse scatter + scalars

#define E 8
#define MAXN 8192
#define NACC 55   // 0:z  1..8:psum  9..16:cnt  17..52:G(upper tri 36)  53:sum  54:sumsq
#define TBLOCKS 32

__device__ unsigned long long g_fkey[MAXN];   // [e:3][p_bits:32][invidx:13]
__device__ float g_prob[MAXN];
__device__ float g_part[TBLOCKS][NACC];
__device__ float g_acc[NACC];

// --------------------------------------------------------------- token ----
__global__ void token_kernel(const float* __restrict__ logits, int N) {
    int i = blockIdx.x * blockDim.x + threadIdx.x;
    float vals[NACC];
#pragma unroll
    for (int k = 0; k < NACC; k++) vals[k] = 0.0f;

    if (i < N) {
        float4 r0 = reinterpret_cast<const float4*>(logits)[2 * i + 0];
        float4 r1 = reinterpret_cast<const float4*>(logits)[2 * i + 1];
        float raw[E] = {r0.x, r0.y, r0.z, r0.w, r1.x, r1.y, r1.z, r1.w};

        float l[E];
        float s = 0.f, s2 = 0.f;
#pragma unroll
        for (int j = 0; j < E; j++) {
            s  += raw[j];
            s2 += raw[j] * raw[j];
            float c = fminf(fmaxf(raw[j], -10.0f), 10.0f);
            l[j] = c / 1.5f;                 // IEEE div, matches JAX clip/temp
        }
        vals[53] = s;
        vals[54] = s2;

        // argmax (first max)
        float m = l[0]; int e = 0;
#pragma unroll
        for (int j = 1; j < E; j++) {
            if (l[j] > m) { m = l[j]; e = j; }
        }

        float sumexp = 0.f;
        float ex[E];
#pragma unroll
        for (int j = 0; j < E; j++) { ex[j] = expf(l[j] - m); sumexp += ex[j]; }
#pragma unroll
        for (int j = 0; j < E; j++) vals[1 + j] = ex[j] / sumexp;

        // static-index one-hot (avoids local-memory spill)
#pragma unroll
        for (int j = 0; j < E; j++) vals[9 + j] = (e == j) ? 1.0f : 0.0f;

        float p = 1.0f / sumexp;             // probs[argmax] exactly as JAX
        g_prob[i] = p;
        // composite key: expert | prob bits | inverted index (stable desc sort)
        unsigned long long key = (unsigned long long)__float_as_uint(p);
        g_fkey[i] = ((unsigned long long)e << 45) | (key << 13)
                  | (unsigned long long)(unsigned)(MAXN - 1 - i);

        float lse = m + logf(sumexp);
        vals[0] = lse * lse;

        int t = 0;
#pragma unroll
        for (int a = 0; a < E; a++)
#pragma unroll
            for (int b = a; b < E; b++) vals[17 + t++] = l[a] * l[b];
    }

    // warp reduce
    int lane = threadIdx.x & 31;
    int wid  = threadIdx.x >> 5;
#pragma unroll
    for (int k = 0; k < NACC; k++) {
        float v = vals[k];
        v += __shfl_down_sync(0xffffffffu, v, 16);
        v += __shfl_down_sync(0xffffffffu, v, 8);
        v += __shfl_down_sync(0xffffffffu, v, 4);
        v += __shfl_down_sync(0xffffffffu, v, 2);
        v += __shfl_down_sync(0xffffffffu, v, 1);
        vals[k] = v;
    }
    __shared__ float sAcc[8][NACC];
    if (lane == 0) {
#pragma unroll
        for (int k = 0; k < NACC; k++) sAcc[wid][k] = vals[k];
    }
    __syncthreads();
    for (int k = threadIdx.x; k < NACC; k += blockDim.x) {
        float v = 0.f;
#pragma unroll
        for (int w = 0; w < 8; w++) v += sAcc[w][k];
        g_part[blockIdx.x][k] = v;     // fully overwritten each replay: no init
    }
}

// ---------------------------------------------------------------- fill ----
__global__ void fill_kernel(uint4* __restrict__ out, size_t n4) {
    // block 0: fold loss partials (hidden under DRAM-bound fill)
    if (blockIdx.x == 0 && threadIdx.x < NACC) {
        int k = threadIdx.x;
        float v = 0.f;
#pragma unroll
        for (int r = 0; r < TBLOCKS; r++) v += g_part[r][k];
        g_acc[k] = v;
    }
    const uint4 z = make_uint4(0u, 0u, 0u, 0u);
    size_t i = (size_t)blockIdx.x * blockDim.x + threadIdx.x;
    size_t stride = (size_t)gridDim.x * blockDim.x;
    for (; i < n4; i += stride) out[i] = z;
}

// -------------------------------------------------------- rank + scatter ----
// Block: 256 threads = 8 warps, each warp owns 4 tokens; lanes split the j loop.
// rank_i = #{j : fkey_j > fkey_i && fkey_j < (e_i+1)<<45}  (branchless, stable)
__global__ void rank_scatter_kernel(float* __restrict__ dispatch_out,
                                    float* __restrict__ combine_out,
                                    float* __restrict__ scalars_out,
                                    int N, int Ccap) {
    extern __shared__ unsigned long long sk[];   // MAXN * 8B = 64KB

    for (int k = threadIdx.x; k < MAXN; k += blockDim.x)
        sk[k] = (k < N) ? g_fkey[k] : 0ull;      // 0 never counts (fk > fki fails)
    __syncthreads();

    int lane = threadIdx.x & 31;
    int wid  = threadIdx.x >> 5;
    int base = (blockIdx.x * 8 + wid) * 4;       // first of this warp's 4 tokens

    unsigned long long fki[4], up[4];
    int cnt[4] = {0, 0, 0, 0};
#pragma unroll
    for (int t = 0; t < 4; t++) {
        int tok = base + t;
        unsigned long long f = (tok < N) ? g_fkey[tok] : ~0ull; // ~0: counts 0
        fki[t] = f;
        up[t]  = (((f >> 45) + 1ull) << 45);
    }

    int n32 = MAXN >> 5;                         // 256 iterations per lane
#pragma unroll 8
    for (int it = 0; it < n32; ++it) {
        unsigned long long fk = sk[it * 32 + lane];
#pragma unroll
        for (int t = 0; t < 4; t++)
            cnt[t] += (int)((fk > fki[t]) & (fk < up[t]));
    }

#pragma unroll
    for (int t = 0; t < 4; t++) {
        int v = cnt[t];
        v += __shfl_down_sync(0xffffffffu, v, 16);
        v += __shfl_down_sync(0xffffffffu, v, 8);
        v += __shfl_down_sync(0xffffffffu, v, 4);
        v += __shfl_down_sync(0xffffffffu, v, 2);
        v += __shfl_down_sync(0xffffffffu, v, 1);
        cnt[t] = __shfl_sync(0xffffffffu, v, 0); // total to all lanes
    }

    if (lane < 4) {
        int tok = base + lane;
        int rank = cnt[lane];
        if (tok < N && rank < Ccap) {
            int e = (int)(fki[lane] >> 45);
            float p = g_prob[tok];
            size_t b = ((size_t)tok * E + e) * (size_t)Ccap + (size_t)rank;
            dispatch_out[b] = 1.0f;
            combine_out[b]  = p;
        }
    }

    // scalar finalize (g_acc folded by fill_kernel)
    if (blockIdx.x == 0 && threadIdx.x == 0) {
        float z_loss = g_acc[0] / (float)N;

        float aux = 0.f;
        for (int e = 0; e < E; e++) aux += g_acc[9 + e] * g_acc[1 + e];
        aux = aux * (float)E / ((float)N * (float)N);

        float G[E][E];
        int t = 0;
        for (int a = 0; a < E; a++)
            for (int b = a; b < E; b++) { G[a][b] = g_acc[17 + t]; G[b][a] = g_acc[17 + t]; t++; }
        float nrm[E];
        for (int a = 0; a < E; a++) nrm[a] = fmaxf(sqrtf(G[a][a]), 1e-12f);
        float div = 0.f;
        for (int a = 0; a < E; a++)
            for (int b = a + 1; b < E; b++) {
                float c = G[a][b] / (nrm[a] * nrm[b]);
                div += 2.0f * c * c;
            }
        div /= (float)(E * (E - 1));

        double M = (double)N * E;
        double sm = (double)g_acc[53], sq = (double)g_acc[54];
        double var = (sq - sm * sm / M) / (M - 1.0);

        scalars_out[0] = z_loss;
        scalars_out[1] = aux;
        scalars_out[2] = div;
        scalars_out[3] = (float)sqrt(var);
    }
}

// -------------------------------------------------------------- launch ----
extern "C" void kernel_launch(void* const* d_in, const int* in_sizes, int n_in,
                              void* d_out, int out_size) {
    const float* logits = (const float*)d_in[1];
    int N = in_sizes[1] / E;                              // 8192
    int Ccap = (int)((3 * N + 2 * E - 1) / (2 * E));      // ceil(1.5*N/E) = 1536
    if (Ccap < 1) Ccap = 1;

    float* out = (float*)d_out;
    size_t D = (size_t)N * E * (size_t)Ccap;
    float* dispatch_out = out;
    float* combine_out  = out + D;
    float* scalars_out  = out + 2 * D;

    // 1) per-token softmax/argmax, keys, loss partials
    token_kernel<<<TBLOCKS, 256>>>(logits, N);

    // 2) zero-fill (the roofline) + partial fold
    size_t n4 = (size_t)out_size >> 2;
    fill_kernel<<<2368, 256>>>((uint4*)d_out, n4);
    size_t rem = (size_t)out_size & 3;
    if (rem) cudaMemsetAsync((float*)d_out + (out_size - rem), 0, rem * sizeof(float));

    // 3) warp-parallel stable rank + scatter + scalars
    static bool attr_set = false;
    if (!attr_set) {
        cudaFuncSetAttribute(rank_scatter_kernel,
                             cudaFuncAttributeMaxDynamicSharedMemorySize,
                             MAXN * (int)sizeof(unsigned long long));
        attr_set = true;
    }
    int rblocks = (N + 31) / 32;                          // 8 warps x 4 tokens
    rank_scatter_kernel<<<rblocks, 256, MAXN * sizeof(unsigned long long)>>>(
        dispatch_out, combine_out, scalars_out, N, Ccap);
}